// round 15
// baseline (speedup 1.0000x reference)
#include <cuda_runtime.h>
#include <cuda_fp16.h>
#include <cstdint>

#define N_NODES 50000
#define N_EDGES 800000
#define IN_F    128
#define OUT_F   256
#define PITCH   136   // fp16 per padded row; 68 words mod 32 = 4 -> conflict-free
#define CAP     64
#define OVF_CAP 1024
#define N_TILES ((N_NODES + 127) / 128)   // 391
#define GEMM_GRID 148
#define BIN_BLOCKS 782
#define CONV_BLOCKS 1568
#define TILE_SPLIT 196                     // chunk boundary (row 25088)
#define ROW_SPLIT  (TILE_SPLIT * 128)      // 25088

// ---------------------------------------------------------------------------
// Device scratch (no allocs allowed)
// ---------------------------------------------------------------------------
__device__ __align__(16) __half g_xh[(size_t)N_NODES * IN_F];    // fp16 x image
__device__ __align__(16) __half g_aggh[(size_t)N_NODES * PITCH]; // fp16 agg, padded
__device__ __align__(16) __half g_B[OUT_F * PITCH];              // W^T fp16 image
__device__ int   g_cnt[N_NODES];
__device__ __align__(8)  uint2 g_edge[(size_t)N_NODES * CAP];
__device__ int   g_ovf_cnt;
__device__ __align__(16) uint4 g_ovf[OVF_CAP];

// ---------------------------------------------------------------------------
// K1: zero counts + convert W -> padded fp16 W^T image.
// ---------------------------------------------------------------------------
__global__ void prep_kernel(const float* __restrict__ W) {
    const int tid = blockIdx.x * blockDim.x + threadIdx.x;
    for (int i = tid; i < N_NODES; i += gridDim.x * blockDim.x) g_cnt[i] = 0;
    if (tid == 0) g_ovf_cnt = 0;

    if (blockIdx.x < 32) {
        const int base = (blockIdx.x * 256 + threadIdx.x) * 4;   // idx = k*256+n
        const float4 w = *reinterpret_cast<const float4*>(W + base);
        const float f[4] = {w.x, w.y, w.z, w.w};
        #pragma unroll
        for (int j = 0; j < 4; j++) {
            const int idx = base + j;
            const int k = idx >> 8;
            const int n = idx & 255;
            g_B[n * PITCH + k] = __float2half(f[j]);
        }
    }
}

// ---------------------------------------------------------------------------
// K2: binning CONCURRENT WITH x fp16 conversion (disjoint block ranges).
// ---------------------------------------------------------------------------
__device__ __forceinline__ void bin_one(int r, int c, float v) {
    const int slot = atomicAdd(&g_cnt[r], 1);
    if (slot < CAP) {
        g_edge[(size_t)r * CAP + slot] = make_uint2((uint32_t)c, __float_as_uint(v));
    } else {
        const int p = atomicAdd(&g_ovf_cnt, 1);
        if (p < OVF_CAP)
            g_ovf[p] = make_uint4((uint32_t)r, (uint32_t)c, __float_as_uint(v), 0u);
    }
}

__global__ void bin_conv_kernel(const int*   __restrict__ erow,
                                const int*   __restrict__ ecol,
                                const float* __restrict__ eval,
                                const float* __restrict__ x) {
    if (blockIdx.x < BIN_BLOCKS) {
        const int base = (blockIdx.x * blockDim.x + threadIdx.x) * 4;
        if (base + 4 <= N_EDGES) {
            const int4   r = __ldg(reinterpret_cast<const int4*>(erow + base));
            const int4   c = __ldg(reinterpret_cast<const int4*>(ecol + base));
            const float4 v = __ldg(reinterpret_cast<const float4*>(eval + base));
            const int s0 = atomicAdd(&g_cnt[r.x], 1);
            const int s1 = atomicAdd(&g_cnt[r.y], 1);
            const int s2 = atomicAdd(&g_cnt[r.z], 1);
            const int s3 = atomicAdd(&g_cnt[r.w], 1);
            if (s0 < CAP) g_edge[(size_t)r.x * CAP + s0] = make_uint2((uint32_t)c.x, __float_as_uint(v.x));
            if (s1 < CAP) g_edge[(size_t)r.y * CAP + s1] = make_uint2((uint32_t)c.y, __float_as_uint(v.y));
            if (s2 < CAP) g_edge[(size_t)r.z * CAP + s2] = make_uint2((uint32_t)c.z, __float_as_uint(v.z));
            if (s3 < CAP) g_edge[(size_t)r.w * CAP + s3] = make_uint2((uint32_t)c.w, __float_as_uint(v.w));
            if (s0 >= CAP) { const int p = atomicAdd(&g_ovf_cnt, 1); if (p < OVF_CAP) g_ovf[p] = make_uint4((uint32_t)r.x, (uint32_t)c.x, __float_as_uint(v.x), 0u); }
            if (s1 >= CAP) { const int p = atomicAdd(&g_ovf_cnt, 1); if (p < OVF_CAP) g_ovf[p] = make_uint4((uint32_t)r.y, (uint32_t)c.y, __float_as_uint(v.y), 0u); }
            if (s2 >= CAP) { const int p = atomicAdd(&g_ovf_cnt, 1); if (p < OVF_CAP) g_ovf[p] = make_uint4((uint32_t)r.z, (uint32_t)c.z, __float_as_uint(v.z), 0u); }
            if (s3 >= CAP) { const int p = atomicAdd(&g_ovf_cnt, 1); if (p < OVF_CAP) g_ovf[p] = make_uint4((uint32_t)r.w, (uint32_t)c.w, __float_as_uint(v.w), 0u); }
        } else {
            for (int e = base; e < N_EDGES; e++)
                bin_one(__ldg(erow + e), __ldg(ecol + e), __ldg(eval + e));
        }
    } else {
        const int cid = (blockIdx.x - BIN_BLOCKS) * blockDim.x + threadIdx.x;
        const int n4 = (N_NODES * IN_F) / 4;
        for (int i = cid; i < n4; i += CONV_BLOCKS * 256) {
            const float4 f = __ldg(reinterpret_cast<const float4*>(x) + i);
            __half2 h0 = __floats2half2_rn(f.x, f.y);
            __half2 h1 = __floats2half2_rn(f.z, f.w);
            uint2 o;
            o.x = *reinterpret_cast<uint32_t*>(&h0);
            o.y = *reinterpret_cast<uint32_t*>(&h1);
            reinterpret_cast<uint2*>(g_xh)[i] = o;
        }
    }
}

// ---------------------------------------------------------------------------
// K3: gather-aggregate over fp16 x for a row range. One warp per row; MLP 8.
// ---------------------------------------------------------------------------
__global__ __launch_bounds__(256)
void gather_kernel(int row_base) {
    const int lane = threadIdx.x & 31;
    const int wid  = threadIdx.x >> 5;
    const int row  = row_base + blockIdx.x * 8 + wid;
    if (row >= N_NODES) return;

    const int raw_cnt = __ldg(g_cnt + row);
    const int cnt = min(raw_cnt, CAP);
    const size_t base = (size_t)row * CAP;

    float4 acc = make_float4(0.f, 0.f, 0.f, 0.f);

    #pragma unroll
    for (int batch = 0; batch < 2; batch++) {
        const int nb = min(cnt - batch * 32, 32);
        if (nb <= 0) break;
        const uint2 ed = __ldg(g_edge + base + batch * 32 + lane);

        for (int j = 0; j < nb; j += 8) {
            uint32_t c[8];
            float    v[8];
            #pragma unroll
            for (int u = 0; u < 8; u++) {
                const bool valid = (j + u) < nb;
                const uint32_t cc = __shfl_sync(~0u, ed.x, (j + u) & 31);
                const uint32_t vv = __shfl_sync(~0u, ed.y, (j + u) & 31);
                c[u] = valid ? cc : 0u;
                v[u] = valid ? __uint_as_float(vv) : 0.f;
            }
            uint2 xv[8];
            #pragma unroll
            for (int u = 0; u < 8; u++)
                xv[u] = __ldg(reinterpret_cast<const uint2*>(
                    g_xh + (size_t)c[u] * IN_F) + lane);
            #pragma unroll
            for (int u = 0; u < 8; u++) {
                const float2 f0 = __half22float2(
                    *reinterpret_cast<const __half2*>(&xv[u].x));
                const float2 f1 = __half22float2(
                    *reinterpret_cast<const __half2*>(&xv[u].y));
                acc.x += v[u] * f0.x;
                acc.y += v[u] * f0.y;
                acc.z += v[u] * f1.x;
                acc.w += v[u] * f1.y;
            }
        }
    }

    if (raw_cnt > CAP) {
        const int n = min(g_ovf_cnt, OVF_CAP);
        for (int i = 0; i < n; i++) {
            const uint4 e = g_ovf[i];
            if ((int)e.x == row) {
                const float v = __uint_as_float(e.z);
                const uint2 xv = __ldg(reinterpret_cast<const uint2*>(
                    g_xh + (size_t)e.y * IN_F) + lane);
                const float2 f0 = __half22float2(
                    *reinterpret_cast<const __half2*>(&xv.x));
                const float2 f1 = __half22float2(
                    *reinterpret_cast<const __half2*>(&xv.y));
                acc.x += v * f0.x; acc.y += v * f0.y;
                acc.z += v * f1.x; acc.w += v * f1.y;
            }
        }
    }

    uint2 ha;
    __half2 h0 = __floats2half2_rn(acc.x, acc.y);
    __half2 h1 = __floats2half2_rn(acc.z, acc.w);
    ha.x = *reinterpret_cast<uint32_t*>(&h0);
    ha.y = *reinterpret_cast<uint32_t*>(&h1);
    *reinterpret_cast<uint2*>(g_aggh + (size_t)row * PITCH + lane * 4) = ha;
}

// ---------------------------------------------------------------------------
// K4: persistent mma.sync fp16 GEMM + bias over a tile range, cp.async A
// double-buffering (R14-proven internals).
// ---------------------------------------------------------------------------
#define GT 256
#define SM_BIAS 0
#define SM_A0   1024
#define SM_A1   (SM_A0 + 128 * PITCH * 2)
#define SM_B    (SM_A1 + 128 * PITCH * 2)
#define SM_TOT  (SM_B + OUT_F * PITCH * 2)          // 140288 B

__device__ __forceinline__ void mma16816(float c[4], uint32_t a0, uint32_t a1,
                                         uint32_t a2, uint32_t a3,
                                         uint32_t b0, uint32_t b1) {
    asm volatile(
        "mma.sync.aligned.m16n8k16.row.col.f32.f16.f16.f32 "
        "{%0,%1,%2,%3}, {%4,%5,%6,%7}, {%8,%9}, {%0,%1,%2,%3};"
        : "+f"(c[0]), "+f"(c[1]), "+f"(c[2]), "+f"(c[3])
        : "r"(a0), "r"(a1), "r"(a2), "r"(a3), "r"(b0), "r"(b1));
}

__device__ __forceinline__ uint32_t smem_u32(const void* p) {
    uint32_t a;
    asm("{ .reg .u64 t; cvta.to.shared.u64 t, %1; cvt.u32.u64 %0, t; }"
        : "=r"(a) : "l"(p));
    return a;
}

__device__ __forceinline__ void stage_a_async(uint32_t sm_dst, int rowbase, int t) {
    #pragma unroll
    for (int i = 0; i < 9; i++) {
        const int idx = t + i * GT;
        if (idx < 128 * 17) {
            const int m = idx / 17;
            const int c = idx % 17;
            const int row = rowbase + m;
            const int sz = (row < N_NODES) ? 16 : 0;
            const __half* src = g_aggh +
                (size_t)(row < N_NODES ? row : 0) * PITCH + c * 8;
            const uint32_t dst = sm_dst + m * (PITCH * 2) + c * 16;
            asm volatile("cp.async.cg.shared.global [%0], [%1], 16, %2;"
                         :: "r"(dst), "l"(src), "r"(sz) : "memory");
        }
    }
    asm volatile("cp.async.commit_group;" ::: "memory");
}

__global__ __launch_bounds__(GT, 1)
void gemm_mma_kernel(const float* __restrict__ bias,
                     float*       __restrict__ out,
                     int tile_base, int tile_end) {
    extern __shared__ char smem[];
    const int t    = threadIdx.x;
    const int lane = t & 31;
    const int wid  = t >> 5;

    float* bias_s = reinterpret_cast<float*>(smem + SM_BIAS);
    __half* Bs = reinterpret_cast<__half*>(smem + SM_B);
    const uint32_t smA[2] = {smem_u32(smem + SM_A0), smem_u32(smem + SM_A1)};
    __half* const Ap[2] = {reinterpret_cast<__half*>(smem + SM_A0),
                           reinterpret_cast<__half*>(smem + SM_A1)};

    const int first = tile_base + blockIdx.x;
    if (first < tile_end)
        stage_a_async(smA[0], first * 128, t);

    if (t < 64)
        reinterpret_cast<float4*>(bias_s)[t] =
            reinterpret_cast<const float4*>(bias)[t];

    {
        const uint4* sb = reinterpret_cast<const uint4*>(g_B);
        uint4* db = reinterpret_cast<uint4*>(Bs);
        #pragma unroll
        for (int i = 0; i < 17; i++)
            db[t + i * GT] = sb[t + i * GT];
    }

    asm volatile("cp.async.wait_group 0;" ::: "memory");
    __syncthreads();

    const int wm = wid >> 2;
    const int wn = wid & 3;
    const int g  = lane >> 2;
    const int tg = lane & 3;
    const int m_base = wm * 64;
    const int n_base = wn * 64;

    int cur = 0;
    for (int tile = first; tile < tile_end; tile += GEMM_GRID) {
        const int rowbase = tile * 128;

        const int next = tile + GEMM_GRID;
        if (next < tile_end)
            stage_a_async(smA[cur ^ 1], next * 128, t);

        const __half* As = Ap[cur];

        float acc[4][8][4];
        #pragma unroll
        for (int mt = 0; mt < 4; mt++)
            #pragma unroll
            for (int nt = 0; nt < 8; nt++)
                #pragma unroll
                for (int j = 0; j < 4; j++)
                    acc[mt][nt][j] = 0.f;

        #pragma unroll
        for (int ks = 0; ks < IN_F; ks += 16) {
            uint32_t af[4][4];
            #pragma unroll
            for (int mt = 0; mt < 4; mt++) {
                const __half* ar =
                    As + (m_base + mt * 16 + g) * PITCH + ks + tg * 2;
                af[mt][0] = *reinterpret_cast<const uint32_t*>(ar);
                af[mt][1] = *reinterpret_cast<const uint32_t*>(ar + 8 * PITCH);
                af[mt][2] = *reinterpret_cast<const uint32_t*>(ar + 8);
                af[mt][3] = *reinterpret_cast<const uint32_t*>(ar + 8 * PITCH + 8);
            }
            uint32_t bf[8][2];
            #pragma unroll
            for (int nt = 0; nt < 8; nt++) {
                const __half* br =
                    Bs + (n_base + nt * 8 + g) * PITCH + ks + tg * 2;
                bf[nt][0] = *reinterpret_cast<const uint32_t*>(br);
                bf[nt][1] = *reinterpret_cast<const uint32_t*>(br + 8);
            }
            #pragma unroll
            for (int mt = 0; mt < 4; mt++)
                #pragma unroll
                for (int nt = 0; nt < 8; nt++)
                    mma16816(acc[mt][nt],
                             af[mt][0], af[mt][1], af[mt][2], af[mt][3],
                             bf[nt][0], bf[nt][1]);
        }

        #pragma unroll
        for (int mt = 0; mt < 4; mt++) {
            const int r0 = rowbase + m_base + mt * 16 + g;
            const int r1 = r0 + 8;
            #pragma unroll
            for (int nt = 0; nt < 8; nt++) {
                const int col = n_base + nt * 8 + tg * 2;
                const float bx = bias_s[col];
                const float by = bias_s[col + 1];
                if (r0 < N_NODES) {
                    float2 o = make_float2(acc[mt][nt][0] + bx, acc[mt][nt][1] + by);
                    *reinterpret_cast<float2*>(out + (size_t)r0 * OUT_F + col) = o;
                }
                if (r1 < N_NODES) {
                    float2 o = make_float2(acc[mt][nt][2] + bx, acc[mt][nt][3] + by);
                    *reinterpret_cast<float2*>(out + (size_t)r1 * OUT_F + col) = o;
                }
            }
        }

        asm volatile("cp.async.wait_group 0;" ::: "memory");
        __syncthreads();
        cur ^= 1;
    }
}

// ---------------------------------------------------------------------------
// Launch: fork-join pipeline — gemm(chunk0) overlaps gather(chunk1).
// ---------------------------------------------------------------------------
extern "C" void kernel_launch(void* const* d_in, const int* in_sizes, int n_in,
                              void* d_out, int out_size) {
    const float* x    = (const float*)d_in[0];
    const int*   erow = (const int*)  d_in[1];
    const int*   ecol = (const int*)  d_in[2];
    const float* eval = (const float*)d_in[3];
    const float* W    = (const float*)d_in[4];
    const float* bias = (const float*)d_in[5];
    float* out = (float*)d_out;

    cudaStream_t s1;
    cudaStreamCreateWithFlags(&s1, cudaStreamNonBlocking);
    cudaEvent_t evA, evB;
    cudaEventCreateWithFlags(&evA, cudaEventDisableTiming);
    cudaEventCreateWithFlags(&evB, cudaEventDisableTiming);

    prep_kernel<<<128, 256>>>(W);
    bin_conv_kernel<<<BIN_BLOCKS + CONV_BLOCKS, 256>>>(erow, ecol, eval, x);

    // gather chunk 0: rows [0, 25088)
    gather_kernel<<<ROW_SPLIT / 8, 256>>>(0);
    cudaEventRecord(evA, 0);

    // gather chunk 1 on s1, concurrent with gemm chunk 0
    cudaStreamWaitEvent(s1, evA, 0);
    gather_kernel<<<(N_NODES - ROW_SPLIT + 7) / 8, 256, 0, s1>>>(ROW_SPLIT);
    cudaEventRecord(evB, s1);

    cudaFuncSetAttribute(gemm_mma_kernel,
                         cudaFuncAttributeMaxDynamicSharedMemorySize, SM_TOT);
    gemm_mma_kernel<<<GEMM_GRID, GT, SM_TOT>>>(bias, out, 0, TILE_SPLIT);

    cudaStreamWaitEvent(0, evB, 0);
    gemm_mma_kernel<<<GEMM_GRID, GT, SM_TOT>>>(bias, out, TILE_SPLIT, N_TILES);
}

// round 16
// speedup vs baseline: 1.2736x; 1.2736x over previous
#include <cuda_runtime.h>
#include <cuda_fp16.h>
#include <cstdint>

#define N_NODES 50000
#define N_EDGES 800000
#define IN_F    128
#define OUT_F   256
#define PITCH   136   // fp16 per padded row; 68 words mod 32 = 4 -> conflict-free
#define CAP     64
#define OVF_CAP 1024
#define N_TILES ((N_NODES + 127) / 128)   // 391
#define GEMM_GRID 148
#define BIN_BLOCKS 782
#define CONV_BLOCKS 1568

// ---------------------------------------------------------------------------
// Device scratch (no allocs allowed)
// ---------------------------------------------------------------------------
__device__ __align__(16) __half g_xh[(size_t)N_NODES * IN_F];    // fp16 x image
__device__ __align__(16) __half g_aggh[(size_t)N_NODES * PITCH]; // fp16 agg, padded
__device__ __align__(16) __half g_B[OUT_F * PITCH];              // W^T fp16 image
__device__ int   g_cnt[N_NODES];
__device__ __align__(8)  uint2 g_edge[(size_t)N_NODES * CAP];
__device__ int   g_ovf_cnt;
__device__ __align__(16) uint4 g_ovf[OVF_CAP];

// ---------------------------------------------------------------------------
// K1: zero counts + convert W -> padded fp16 W^T image.
// ---------------------------------------------------------------------------
__global__ void prep_kernel(const float* __restrict__ W) {
    const int tid = blockIdx.x * blockDim.x + threadIdx.x;
    for (int i = tid; i < N_NODES; i += gridDim.x * blockDim.x) g_cnt[i] = 0;
    if (tid == 0) g_ovf_cnt = 0;

    if (blockIdx.x < 32) {
        const int base = (blockIdx.x * 256 + threadIdx.x) * 4;   // idx = k*256+n
        const float4 w = *reinterpret_cast<const float4*>(W + base);
        const float f[4] = {w.x, w.y, w.z, w.w};
        #pragma unroll
        for (int j = 0; j < 4; j++) {
            const int idx = base + j;
            const int k = idx >> 8;
            const int n = idx & 255;
            g_B[n * PITCH + k] = __float2half(f[j]);
        }
    }
}

// ---------------------------------------------------------------------------
// K2: binning CONCURRENT WITH x fp16 conversion (disjoint block ranges).
// ---------------------------------------------------------------------------
__device__ __forceinline__ void bin_one(int r, int c, float v) {
    const int slot = atomicAdd(&g_cnt[r], 1);
    if (slot < CAP) {
        g_edge[(size_t)r * CAP + slot] = make_uint2((uint32_t)c, __float_as_uint(v));
    } else {
        const int p = atomicAdd(&g_ovf_cnt, 1);
        if (p < OVF_CAP)
            g_ovf[p] = make_uint4((uint32_t)r, (uint32_t)c, __float_as_uint(v), 0u);
    }
}

__global__ void bin_conv_kernel(const int*   __restrict__ erow,
                                const int*   __restrict__ ecol,
                                const float* __restrict__ eval,
                                const float* __restrict__ x) {
    if (blockIdx.x < BIN_BLOCKS) {
        const int base = (blockIdx.x * blockDim.x + threadIdx.x) * 4;
        if (base + 4 <= N_EDGES) {
            const int4   r = __ldg(reinterpret_cast<const int4*>(erow + base));
            const int4   c = __ldg(reinterpret_cast<const int4*>(ecol + base));
            const float4 v = __ldg(reinterpret_cast<const float4*>(eval + base));
            const int s0 = atomicAdd(&g_cnt[r.x], 1);
            const int s1 = atomicAdd(&g_cnt[r.y], 1);
            const int s2 = atomicAdd(&g_cnt[r.z], 1);
            const int s3 = atomicAdd(&g_cnt[r.w], 1);
            if (s0 < CAP) g_edge[(size_t)r.x * CAP + s0] = make_uint2((uint32_t)c.x, __float_as_uint(v.x));
            if (s1 < CAP) g_edge[(size_t)r.y * CAP + s1] = make_uint2((uint32_t)c.y, __float_as_uint(v.y));
            if (s2 < CAP) g_edge[(size_t)r.z * CAP + s2] = make_uint2((uint32_t)c.z, __float_as_uint(v.z));
            if (s3 < CAP) g_edge[(size_t)r.w * CAP + s3] = make_uint2((uint32_t)c.w, __float_as_uint(v.w));
            if (s0 >= CAP) { const int p = atomicAdd(&g_ovf_cnt, 1); if (p < OVF_CAP) g_ovf[p] = make_uint4((uint32_t)r.x, (uint32_t)c.x, __float_as_uint(v.x), 0u); }
            if (s1 >= CAP) { const int p = atomicAdd(&g_ovf_cnt, 1); if (p < OVF_CAP) g_ovf[p] = make_uint4((uint32_t)r.y, (uint32_t)c.y, __float_as_uint(v.y), 0u); }
            if (s2 >= CAP) { const int p = atomicAdd(&g_ovf_cnt, 1); if (p < OVF_CAP) g_ovf[p] = make_uint4((uint32_t)r.z, (uint32_t)c.z, __float_as_uint(v.z), 0u); }
            if (s3 >= CAP) { const int p = atomicAdd(&g_ovf_cnt, 1); if (p < OVF_CAP) g_ovf[p] = make_uint4((uint32_t)r.w, (uint32_t)c.w, __float_as_uint(v.w), 0u); }
        } else {
            for (int e = base; e < N_EDGES; e++)
                bin_one(__ldg(erow + e), __ldg(ecol + e), __ldg(eval + e));
        }
    } else {
        const int cid = (blockIdx.x - BIN_BLOCKS) * blockDim.x + threadIdx.x;
        const int n4 = (N_NODES * IN_F) / 4;
        for (int i = cid; i < n4; i += CONV_BLOCKS * 256) {
            const float4 f = __ldg(reinterpret_cast<const float4*>(x) + i);
            __half2 h0 = __floats2half2_rn(f.x, f.y);
            __half2 h1 = __floats2half2_rn(f.z, f.w);
            uint2 o;
            o.x = *reinterpret_cast<uint32_t*>(&h0);
            o.y = *reinterpret_cast<uint32_t*>(&h1);
            reinterpret_cast<uint2*>(g_xh)[i] = o;
        }
    }
}

// ---------------------------------------------------------------------------
// K3: gather-aggregate over fp16 x. One warp per row. Edges read via
// same-address broadcast __ldg (no shfl); full unpredicated 8-groups + tail.
// ---------------------------------------------------------------------------
__global__ __launch_bounds__(256)
void gather_kernel() {
    const int lane = threadIdx.x & 31;
    const int wid  = threadIdx.x >> 5;
    const int row  = blockIdx.x * 8 + wid;
    if (row >= N_NODES) return;

    const int raw_cnt = __ldg(g_cnt + row);
    const int cnt = min(raw_cnt, CAP);
    const uint2* ep = g_edge + (size_t)row * CAP;

    float4 acc = make_float4(0.f, 0.f, 0.f, 0.f);

    int j = 0;
    for (; j + 8 <= cnt; j += 8) {
        uint2 e[8];
        #pragma unroll
        for (int u = 0; u < 8; u++)
            e[u] = __ldg(ep + j + u);          // same-address broadcast
        uint2 xv[8];
        #pragma unroll
        for (int u = 0; u < 8; u++)
            xv[u] = __ldg(reinterpret_cast<const uint2*>(
                g_xh + (size_t)e[u].x * IN_F) + lane);
        #pragma unroll
        for (int u = 0; u < 8; u++) {
            const float v = __uint_as_float(e[u].y);
            const float2 f0 = __half22float2(
                *reinterpret_cast<const __half2*>(&xv[u].x));
            const float2 f1 = __half22float2(
                *reinterpret_cast<const __half2*>(&xv[u].y));
            acc.x += v * f0.x;
            acc.y += v * f0.y;
            acc.z += v * f1.x;
            acc.w += v * f1.y;
        }
    }
    for (; j < cnt; j++) {
        const uint2 e = __ldg(ep + j);
        const float v = __uint_as_float(e.y);
        const uint2 xv = __ldg(reinterpret_cast<const uint2*>(
            g_xh + (size_t)e.x * IN_F) + lane);
        const float2 f0 = __half22float2(
            *reinterpret_cast<const __half2*>(&xv.x));
        const float2 f1 = __half22float2(
            *reinterpret_cast<const __half2*>(&xv.y));
        acc.x += v * f0.x; acc.y += v * f0.y;
        acc.z += v * f1.x; acc.w += v * f1.y;
    }

    if (raw_cnt > CAP) {
        const int n = min(g_ovf_cnt, OVF_CAP);
        for (int i = 0; i < n; i++) {
            const uint4 e = g_ovf[i];
            if ((int)e.x == row) {
                const float v = __uint_as_float(e.z);
                const uint2 xv = __ldg(reinterpret_cast<const uint2*>(
                    g_xh + (size_t)e.y * IN_F) + lane);
                const float2 f0 = __half22float2(
                    *reinterpret_cast<const __half2*>(&xv.x));
                const float2 f1 = __half22float2(
                    *reinterpret_cast<const __half2*>(&xv.y));
                acc.x += v * f0.x; acc.y += v * f0.y;
                acc.z += v * f1.x; acc.w += v * f1.y;
            }
        }
    }

    uint2 ha;
    __half2 h0 = __floats2half2_rn(acc.x, acc.y);
    __half2 h1 = __floats2half2_rn(acc.z, acc.w);
    ha.x = *reinterpret_cast<uint32_t*>(&h0);
    ha.y = *reinterpret_cast<uint32_t*>(&h1);
    *reinterpret_cast<uint2*>(g_aggh + (size_t)row * PITCH + lane * 4) = ha;
}

// ---------------------------------------------------------------------------
// K4: persistent mma.sync fp16 GEMM + bias, double-buffered A via cp.async
// (R14-proven, single full-range launch).
// ---------------------------------------------------------------------------
#define GT 256
#define SM_BIAS 0
#define SM_A0   1024
#define SM_A1   (SM_A0 + 128 * PITCH * 2)
#define SM_B    (SM_A1 + 128 * PITCH * 2)
#define SM_TOT  (SM_B + OUT_F * PITCH * 2)          // 140288 B

__device__ __forceinline__ void mma16816(float c[4], uint32_t a0, uint32_t a1,
                                         uint32_t a2, uint32_t a3,
                                         uint32_t b0, uint32_t b1) {
    asm volatile(
        "mma.sync.aligned.m16n8k16.row.col.f32.f16.f16.f32 "
        "{%0,%1,%2,%3}, {%4,%5,%6,%7}, {%8,%9}, {%0,%1,%2,%3};"
        : "+f"(c[0]), "+f"(c[1]), "+f"(c[2]), "+f"(c[3])
        : "r"(a0), "r"(a1), "r"(a2), "r"(a3), "r"(b0), "r"(b1));
}

__device__ __forceinline__ uint32_t smem_u32(const void* p) {
    uint32_t a;
    asm("{ .reg .u64 t; cvta.to.shared.u64 t, %1; cvt.u32.u64 %0, t; }"
        : "=r"(a) : "l"(p));
    return a;
}

__device__ __forceinline__ void stage_a_async(uint32_t sm_dst, int rowbase, int t) {
    #pragma unroll
    for (int i = 0; i < 9; i++) {
        const int idx = t + i * GT;
        if (idx < 128 * 17) {
            const int m = idx / 17;
            const int c = idx % 17;
            const int row = rowbase + m;
            const int sz = (row < N_NODES) ? 16 : 0;
            const __half* src = g_aggh +
                (size_t)(row < N_NODES ? row : 0) * PITCH + c * 8;
            const uint32_t dst = sm_dst + m * (PITCH * 2) + c * 16;
            asm volatile("cp.async.cg.shared.global [%0], [%1], 16, %2;"
                         :: "r"(dst), "l"(src), "r"(sz) : "memory");
        }
    }
    asm volatile("cp.async.commit_group;" ::: "memory");
}

__global__ __launch_bounds__(GT, 1)
void gemm_mma_kernel(const float* __restrict__ bias,
                     float*       __restrict__ out) {
    extern __shared__ char smem[];
    const int t    = threadIdx.x;
    const int lane = t & 31;
    const int wid  = t >> 5;

    float* bias_s = reinterpret_cast<float*>(smem + SM_BIAS);
    __half* Bs = reinterpret_cast<__half*>(smem + SM_B);
    const uint32_t smA[2] = {smem_u32(smem + SM_A0), smem_u32(smem + SM_A1)};
    __half* const Ap[2] = {reinterpret_cast<__half*>(smem + SM_A0),
                           reinterpret_cast<__half*>(smem + SM_A1)};

    if (blockIdx.x < N_TILES)
        stage_a_async(smA[0], blockIdx.x * 128, t);

    if (t < 64)
        reinterpret_cast<float4*>(bias_s)[t] =
            reinterpret_cast<const float4*>(bias)[t];

    {
        const uint4* sb = reinterpret_cast<const uint4*>(g_B);
        uint4* db = reinterpret_cast<uint4*>(Bs);
        #pragma unroll
        for (int i = 0; i < 17; i++)
            db[t + i * GT] = sb[t + i * GT];
    }

    asm volatile("cp.async.wait_group 0;" ::: "memory");
    __syncthreads();

    const int wm = wid >> 2;
    const int wn = wid & 3;
    const int g  = lane >> 2;
    const int tg = lane & 3;
    const int m_base = wm * 64;
    const int n_base = wn * 64;

    int cur = 0;
    for (int tile = blockIdx.x; tile < N_TILES; tile += GEMM_GRID) {
        const int rowbase = tile * 128;

        const int next = tile + GEMM_GRID;
        if (next < N_TILES)
            stage_a_async(smA[cur ^ 1], next * 128, t);

        const __half* As = Ap[cur];

        float acc[4][8][4];
        #pragma unroll
        for (int mt = 0; mt < 4; mt++)
            #pragma unroll
            for (int nt = 0; nt < 8; nt++)
                #pragma unroll
                for (int j = 0; j < 4; j++)
                    acc[mt][nt][j] = 0.f;

        #pragma unroll
        for (int ks = 0; ks < IN_F; ks += 16) {
            uint32_t af[4][4];
            #pragma unroll
            for (int mt = 0; mt < 4; mt++) {
                const __half* ar =
                    As + (m_base + mt * 16 + g) * PITCH + ks + tg * 2;
                af[mt][0] = *reinterpret_cast<const uint32_t*>(ar);
                af[mt][1] = *reinterpret_cast<const uint32_t*>(ar + 8 * PITCH);
                af[mt][2] = *reinterpret_cast<const uint32_t*>(ar + 8);
                af[mt][3] = *reinterpret_cast<const uint32_t*>(ar + 8 * PITCH + 8);
            }
            uint32_t bf[8][2];
            #pragma unroll
            for (int nt = 0; nt < 8; nt++) {
                const __half* br =
                    Bs + (n_base + nt * 8 + g) * PITCH + ks + tg * 2;
                bf[nt][0] = *reinterpret_cast<const uint32_t*>(br);
                bf[nt][1] = *reinterpret_cast<const uint32_t*>(br + 8);
            }
            #pragma unroll
            for (int mt = 0; mt < 4; mt++)
                #pragma unroll
                for (int nt = 0; nt < 8; nt++)
                    mma16816(acc[mt][nt],
                             af[mt][0], af[mt][1], af[mt][2], af[mt][3],
                             bf[nt][0], bf[nt][1]);
        }

        #pragma unroll
        for (int mt = 0; mt < 4; mt++) {
            const int r0 = rowbase + m_base + mt * 16 + g;
            const int r1 = r0 + 8;
            #pragma unroll
            for (int nt = 0; nt < 8; nt++) {
                const int col = n_base + nt * 8 + tg * 2;
                const float bx = bias_s[col];
                const float by = bias_s[col + 1];
                if (r0 < N_NODES) {
                    float2 o = make_float2(acc[mt][nt][0] + bx, acc[mt][nt][1] + by);
                    *reinterpret_cast<float2*>(out + (size_t)r0 * OUT_F + col) = o;
                }
                if (r1 < N_NODES) {
                    float2 o = make_float2(acc[mt][nt][2] + bx, acc[mt][nt][3] + by);
                    *reinterpret_cast<float2*>(out + (size_t)r1 * OUT_F + col) = o;
                }
            }
        }

        asm volatile("cp.async.wait_group 0;" ::: "memory");
        __syncthreads();
        cur ^= 1;
    }
}

// ---------------------------------------------------------------------------
// Launch (single stream, R14 structure)
// ---------------------------------------------------------------------------
extern "C" void kernel_launch(void* const* d_in, const int* in_sizes, int n_in,
                              void* d_out, int out_size) {
    const float* x    = (const float*)d_in[0];
    const int*   erow = (const int*)  d_in[1];
    const int*   ecol = (const int*)  d_in[2];
    const float* eval = (const float*)d_in[3];
    const float* W    = (const float*)d_in[4];
    const float* bias = (const float*)d_in[5];
    float* out = (float*)d_out;

    prep_kernel<<<128, 256>>>(W);
    bin_conv_kernel<<<BIN_BLOCKS + CONV_BLOCKS, 256>>>(erow, ecol, eval, x);
    gather_kernel<<<(N_NODES + 7) / 8, 256>>>();

    cudaFuncSetAttribute(gemm_mma_kernel,
                         cudaFuncAttributeMaxDynamicSharedMemorySize, SM_TOT);
    gemm_mma_kernel<<<GEMM_GRID, GT, SM_TOT>>>(bias, out);
}